// round 12
// baseline (speedup 1.0000x reference)
#include <cuda_runtime.h>
#include <cuda_bf16.h>
#include <cstdint>

#define DIMC   128
#define LTOK   32768
#define QSCALE (0.25f * 1.4426950408889634f)   // HD^-0.5 * log2(e)

// ---------------- smem byte offsets ----------------
// Qh/Ql, Kh/Kl: 512 rows x 24 bf16 (48B stride; 16 used) -- conflict-free frag loads
// VTh/VTl: V^T [16 d][520 keys] bf16 (1040B stride; 512 used)
// wsm: conv weights [16 c][125 taps] fp32
// cbuf: conv output+bias [512 tokens][20 floats] (16 used)
#define SM_QH   0
#define SM_QL   24576
#define SM_KH   49152
#define SM_KL   73728
#define SM_VTH  98304
#define SM_VTL  114944
#define SM_WSM  131584
#define SM_CBUF 139584
#define SMEM_TOTAL 180544

// ---------------- helpers ----------------
__device__ __forceinline__ float ex2f(float x) {
    float y; asm("ex2.approx.f32 %0, %1;" : "=f"(y) : "f"(x)); return y;
}
// pack: low 16 bits = bf16(a), high 16 bits = bf16(b)
__device__ __forceinline__ uint32_t pkbf2(float a, float b) {
    uint32_t r;
    asm("cvt.rn.satfinite.bf16x2.f32 %0, %1, %2;" : "=r"(r) : "f"(b), "f"(a));
    return r;
}
// m16n8k16 row.col bf16 MMA, fp32 accumulate in-place
__device__ __forceinline__ void mma16816(float* c, const uint32_t* a,
                                          uint32_t b0, uint32_t b1) {
    asm volatile(
        "mma.sync.aligned.m16n8k16.row.col.f32.bf16.bf16.f32 "
        "{%0,%1,%2,%3}, {%4,%5,%6,%7}, {%8,%9}, {%0,%1,%2,%3};"
        : "+f"(c[0]), "+f"(c[1]), "+f"(c[2]), "+f"(c[3])
        : "r"(a[0]), "r"(a[1]), "r"(a[2]), "r"(a[3]), "r"(b0), "r"(b1));
}
// split fp32 pair -> hi/lo bf16x2, store into padded row (48B stride)
__device__ __forceinline__ void split_store(char* hib, char* lob, int row, int i,
                                            float a, float b) {
    uint32_t hp = pkbf2(a, b);
    float r0 = a - __uint_as_float(hp << 16);
    float r1 = b - __uint_as_float(hp & 0xFFFF0000u);
    uint32_t lp = pkbf2(r0, r1);
    *(uint32_t*)(hib + row * 48 + i * 4) = hp;
    *(uint32_t*)(lob + row * 48 + i * 4) = lp;
}

// =============================== kernel ====================================
__global__ void __launch_bounds__(512, 1)
lepe_attn_hmma(const float* __restrict__ qkv,
               const float* __restrict__ wconv,
               const float* __restrict__ bias,
               float* __restrict__ out)
{
    extern __shared__ char sm[];
    float* wsm  = (float*)(sm + SM_WSM);
    float* cbuf = (float*)(sm + SM_CBUF);

    const int tid    = threadIdx.x;
    const int warpid = tid >> 5;          // 0..15
    const int lane   = tid & 31;

    const int wh   = blockIdx.x;          // 1024 = 128 windows * 8 heads
    const int head = wh & 7;
    const int win  = wh >> 3;
    const int b    = win >> 6;
    const int w_o  = (win >> 3) & 7;
    const int s_o  = win & 7;
    const int MOFF = 2 * LTOK * DIMC;

    // ================= prologue: convert Q/K/V to split-bf16 =================
    {
        const int tt = tid;                            // token 0..511
        const int hi = tt >> 4, wi = (tt >> 2) & 3, si = tt & 3;
        const int l  = hi * 1024 + (w_o * 4 + wi) * 32 + s_o * 4 + si;
        const int gb = (b * LTOK + l) * DIMC + head * 16;

        const float4* qg = (const float4*)(qkv + gb);
        const float4* kg = (const float4*)(qkv + MOFF + gb);
        const float4* vg = (const float4*)(qkv + 2 * MOFF + gb);
        float4 q4[4] = {qg[0], qg[1], qg[2], qg[3]};
        float4 k4[4] = {kg[0], kg[1], kg[2], kg[3]};
        float4 v4[4] = {vg[0], vg[1], vg[2], vg[3]};

#pragma unroll
        for (int i = 0; i < 4; ++i) {
            split_store(sm + SM_QH, sm + SM_QL, tt, 2*i,
                        q4[i].x * QSCALE, q4[i].y * QSCALE);
            split_store(sm + SM_QH, sm + SM_QL, tt, 2*i+1,
                        q4[i].z * QSCALE, q4[i].w * QSCALE);
            split_store(sm + SM_KH, sm + SM_KL, tt, 2*i,   k4[i].x, k4[i].y);
            split_store(sm + SM_KH, sm + SM_KL, tt, 2*i+1, k4[i].z, k4[i].w);
        }
        float vv[16] = {v4[0].x,v4[0].y,v4[0].z,v4[0].w, v4[1].x,v4[1].y,v4[1].z,v4[1].w,
                        v4[2].x,v4[2].y,v4[2].z,v4[2].w, v4[3].x,v4[3].y,v4[3].z,v4[3].w};
#pragma unroll
        for (int d = 0; d < 16; ++d) {
            uint32_t hb = pkbf2(vv[d], 0.f) & 0xFFFFu;
            float lo = vv[d] - __uint_as_float(hb << 16);
            uint32_t lb = pkbf2(lo, 0.f) & 0xFFFFu;
            *(unsigned short*)(sm + SM_VTH + d * 1040 + tt * 2) = (unsigned short)hb;
            *(unsigned short*)(sm + SM_VTL + d * 1040 + tt * 2) = (unsigned short)lb;
        }
    }
    // conv weights
    for (int i = tid; i < 16 * 125; i += 512) {
        int c = i / 125, tap = i % 125;
        wsm[i] = wconv[(head * 16 + c) * 125 + tap];
    }
    __syncthreads();

    // ================= LePE conv (registers + shuffles) =================
    // lane = H row (0..31); warp w handles channel w (16 warps, 16 channels)
    {
        const int c = warpid;
        float bv = __ldg(bias + head * 16 + c);
        float vr[16], co[16];
        int gb = (b * LTOK + lane * 1024 + (w_o * 4) * 32 + s_o * 4) * DIMC
               + head * 16 + c;
#pragma unroll
        for (int j = 0; j < 16; ++j) {
            vr[j] = __ldg(qkv + 2 * MOFF + gb + ((j >> 2) * 32 + (j & 3)) * DIMC);
            co[j] = 0.f;
        }
#pragma unroll
        for (int dh = 0; dh < 5; ++dh) {
            int hs = lane + dh - 2;
            bool ok = (unsigned)hs < 32u;
            int src = hs < 0 ? 0 : (hs > 31 ? 31 : hs);
            float tmp[16];
#pragma unroll
            for (int j = 0; j < 16; ++j)
                tmp[j] = __shfl_sync(0xFFFFFFFFu, vr[j], src);
            if (ok) {
                const float* wc = wsm + c * 125 + dh * 25;
#pragma unroll
                for (int dw = 0; dw < 5; ++dw)
#pragma unroll
                    for (int ds = 0; ds < 5; ++ds) {
                        float wt = wc[dw * 5 + ds];
#pragma unroll
                        for (int w = 0; w < 4; ++w)
#pragma unroll
                            for (int s = 0; s < 4; ++s) {
                                int ww = w + dw - 2, ss = s + ds - 2;
                                if (ww >= 0 && ww < 4 && ss >= 0 && ss < 4)
                                    co[w * 4 + s] += wt * tmp[ww * 4 + ss];
                            }
                    }
            }
        }
#pragma unroll
        for (int j = 0; j < 16; ++j)
            cbuf[(lane * 16 + j) * 20 + c] = co[j] + bv;
    }
    __syncthreads();

    // ================= attention: per-warp 32 q-rows, flash loop =============
    // Q A-fragments (2 m-tiles x hi/lo)
    uint32_t qh[2][4], ql[2][4];
#pragma unroll
    for (int mt = 0; mt < 2; ++mt) {
        int r0 = warpid * 32 + mt * 16 + (lane >> 2);
        const char* qro = sm + SM_QH + r0 * 48 + (lane & 3) * 4;
        qh[mt][0] = *(const uint32_t*)qro;
        qh[mt][1] = *(const uint32_t*)(qro + 8 * 48);
        qh[mt][2] = *(const uint32_t*)(qro + 16);
        qh[mt][3] = *(const uint32_t*)(qro + 8 * 48 + 16);
        const char* qrl = sm + SM_QL + r0 * 48 + (lane & 3) * 4;
        ql[mt][0] = *(const uint32_t*)qrl;
        ql[mt][1] = *(const uint32_t*)(qrl + 8 * 48);
        ql[mt][2] = *(const uint32_t*)(qrl + 16);
        ql[mt][3] = *(const uint32_t*)(qrl + 8 * 48 + 16);
    }

    float o[2][2][4];
    float den[2][2];
#pragma unroll
    for (int mt = 0; mt < 2; ++mt) {
        den[mt][0] = den[mt][1] = 0.f;
#pragma unroll
        for (int nt = 0; nt < 2; ++nt)
#pragma unroll
            for (int j = 0; j < 4; ++j) o[mt][nt][j] = 0.f;
    }

#pragma unroll 1
    for (int ch = 0; ch < 32; ++ch) {
        uint32_t pah[2][4], pal[2][4];
        // ---- S phase: scores for 16 keys, exp2, split-bf16 P frags ----
#pragma unroll
        for (int nt = 0; nt < 2; ++nt) {
            int krow = ch * 16 + nt * 8 + (lane >> 2);
            const char* kro = sm + SM_KH + krow * 48 + (lane & 3) * 4;
            uint32_t kh0 = *(const uint32_t*)kro;
            uint32_t kh1 = *(const uint32_t*)(kro + 16);
            const char* krl = sm + SM_KL + krow * 48 + (lane & 3) * 4;
            uint32_t kl0 = *(const uint32_t*)krl;
            uint32_t kl1 = *(const uint32_t*)(krl + 16);
#pragma unroll
            for (int mt = 0; mt < 2; ++mt) {
                float s[4] = {0.f, 0.f, 0.f, 0.f};
                mma16816(s, qh[mt], kh0, kh1);
                mma16816(s, qh[mt], kl0, kl1);
                mma16816(s, ql[mt], kh0, kh1);
                float p0 = ex2f(s[0]), p1 = ex2f(s[1]);
                float p2 = ex2f(s[2]), p3 = ex2f(s[3]);
                den[mt][0] += p0 + p1;
                den[mt][1] += p2 + p3;
                uint32_t h01 = pkbf2(p0, p1), h23 = pkbf2(p2, p3);
                uint32_t l01 = pkbf2(p0 - __uint_as_float(h01 << 16),
                                     p1 - __uint_as_float(h01 & 0xFFFF0000u));
                uint32_t l23 = pkbf2(p2 - __uint_as_float(h23 << 16),
                                     p3 - __uint_as_float(h23 & 0xFFFF0000u));
                pah[mt][nt * 2 + 0] = h01;
                pah[mt][nt * 2 + 1] = h23;
                pal[mt][nt * 2 + 0] = l01;
                pal[mt][nt * 2 + 1] = l23;
            }
        }
        // ---- PV phase ----
#pragma unroll
        for (int ntd = 0; ntd < 2; ++ntd) {
            int vrow = ntd * 8 + (lane >> 2);
            int kof  = ch * 16 + (lane & 3) * 2;
            const char* vh = sm + SM_VTH + vrow * 1040 + kof * 2;
            uint32_t vh0 = *(const uint32_t*)vh;
            uint32_t vh1 = *(const uint32_t*)(vh + 16);
            const char* vl = sm + SM_VTL + vrow * 1040 + kof * 2;
            uint32_t vl0 = *(const uint32_t*)vl;
            uint32_t vl1 = *(const uint32_t*)(vl + 16);
#pragma unroll
            for (int mt = 0; mt < 2; ++mt) {
                mma16816(o[mt][ntd], pah[mt], vh0, vh1);
                mma16816(o[mt][ntd], pal[mt], vh0, vh1);
                mma16816(o[mt][ntd], pah[mt], vl0, vl1);
            }
        }
    }

    // ================= output: normalize + conv + store =================
#pragma unroll
    for (int mt = 0; mt < 2; ++mt) {
#pragma unroll
        for (int rh = 0; rh < 2; ++rh) {
            float d = den[mt][rh];
            d += __shfl_xor_sync(0xFFFFFFFFu, d, 1);
            d += __shfl_xor_sync(0xFFFFFFFFu, d, 2);
            den[mt][rh] = d;
        }
#pragma unroll
        for (int rh = 0; rh < 2; ++rh) {
            int t = warpid * 32 + mt * 16 + (lane >> 2) + rh * 8;
            float inv = 1.0f / den[mt][rh];
            int hi = t >> 4, wi = (t >> 2) & 3, si = t & 3;
            int l  = hi * 1024 + (w_o * 4 + wi) * 32 + s_o * 4 + si;
            float* og = out + (size_t)(b * LTOK + l) * DIMC + head * 16;
#pragma unroll
            for (int ntd = 0; ntd < 2; ++ntd) {
                int dcol = ntd * 8 + (lane & 3) * 2;
                float c0 = o[mt][ntd][rh * 2 + 0] * inv + cbuf[t * 20 + dcol];
                float c1 = o[mt][ntd][rh * 2 + 1] * inv + cbuf[t * 20 + dcol + 1];
                *(float2*)(og + dcol) = make_float2(c0, c1);
            }
        }
    }
}

extern "C" void kernel_launch(void* const* d_in, const int* in_sizes, int n_in,
                              void* d_out, int out_size)
{
    (void)in_sizes; (void)n_in; (void)out_size;
    const float* qkv  = (const float*)d_in[0];
    const float* w    = (const float*)d_in[1];
    const float* bias = (const float*)d_in[2];
    float* out = (float*)d_out;

    cudaFuncSetAttribute(lepe_attn_hmma,
                         cudaFuncAttributeMaxDynamicSharedMemorySize, SMEM_TOTAL);
    lepe_attn_hmma<<<1024, 512, SMEM_TOTAL>>>(qkv, w, bias, out);
}

// round 13
// speedup vs baseline: 1.1552x; 1.1552x over previous
#include <cuda_runtime.h>
#include <cuda_fp16.h>
#include <cstdint>

#define DIMC   128
#define LTOK   32768
#define QSCALE (0.25f * 1.4426950408889634f)   // HD^-0.5 * log2(e)

// ---------------- smem byte offsets ----------------
// Qh/Ql, Kh/Kl: 512 rows x 24 fp16 (48B stride; 16 used) -- conflict-free frag loads
// VTh/VTl: V^T [16 d][520 keys] fp16 (1040B stride; 512 used)
// wsm: conv weights [16 c][125 taps] fp32
// cbuf: conv output+bias [512 tokens][20 floats] (16 used)
#define SM_QH   0
#define SM_QL   24576
#define SM_KH   49152
#define SM_KL   73728
#define SM_VTH  98304
#define SM_VTL  114944
#define SM_WSM  131584
#define SM_CBUF 139584
#define SMEM_TOTAL 180544

// ---------------- helpers ----------------
__device__ __forceinline__ float ex2f(float x) {
    float y; asm("ex2.approx.f32 %0, %1;" : "=f"(y) : "f"(x)); return y;
}
// pack: low 16 bits = fp16(a), high 16 bits = fp16(b)
__device__ __forceinline__ uint32_t pkf16(float a, float b) {
    uint32_t r;
    asm("cvt.rn.f16x2.f32 %0, %1, %2;" : "=r"(r) : "f"(b), "f"(a));
    return r;
}
__device__ __forceinline__ float h2f_lo(uint32_t p) {
    return __half2float(__ushort_as_half((unsigned short)(p & 0xFFFFu)));
}
__device__ __forceinline__ float h2f_hi(uint32_t p) {
    return __half2float(__ushort_as_half((unsigned short)(p >> 16)));
}
// m16n8k16 row.col fp16 MMA, fp32 accumulate in-place
__device__ __forceinline__ void mma16816(float* c, const uint32_t* a,
                                          uint32_t b0, uint32_t b1) {
    asm volatile(
        "mma.sync.aligned.m16n8k16.row.col.f32.f16.f16.f32 "
        "{%0,%1,%2,%3}, {%4,%5,%6,%7}, {%8,%9}, {%0,%1,%2,%3};"
        : "+f"(c[0]), "+f"(c[1]), "+f"(c[2]), "+f"(c[3])
        : "r"(a[0]), "r"(a[1]), "r"(a[2]), "r"(a[3]), "r"(b0), "r"(b1));
}
// split fp32 pair -> hi/lo fp16x2, store into padded row (48B stride)
__device__ __forceinline__ void split_store(char* hib, char* lob, int row, int i,
                                            float a, float b) {
    uint32_t hp = pkf16(a, b);
    float r0 = a - h2f_lo(hp);
    float r1 = b - h2f_hi(hp);
    uint32_t lp = pkf16(r0, r1);
    *(uint32_t*)(hib + row * 48 + i * 4) = hp;
    *(uint32_t*)(lob + row * 48 + i * 4) = lp;
}

// =============================== kernel ====================================
__global__ void __launch_bounds__(256, 1)
lepe_attn_hmma(const float* __restrict__ qkv,
               const float* __restrict__ wconv,
               const float* __restrict__ bias,
               float* __restrict__ out)
{
    extern __shared__ char sm[];
    float* wsm  = (float*)(sm + SM_WSM);
    float* cbuf = (float*)(sm + SM_CBUF);

    const int tid    = threadIdx.x;
    const int warpid = tid >> 5;          // 0..7
    const int lane   = tid & 31;

    const int wh   = blockIdx.x;          // 1024 = 128 windows * 8 heads
    const int head = wh & 7;
    const int win  = wh >> 3;
    const int b    = win >> 6;
    const int w_o  = (win >> 3) & 7;
    const int s_o  = win & 7;
    const int MOFF = 2 * LTOK * DIMC;

    // ================= prologue: convert Q/K/V to split-fp16 =================
#pragma unroll
    for (int tk = 0; tk < 2; ++tk) {
        const int tt = tid + tk * 256;                 // token 0..511
        const int hi = tt >> 4, wi = (tt >> 2) & 3, si = tt & 3;
        const int l  = hi * 1024 + (w_o * 4 + wi) * 32 + s_o * 4 + si;
        const int gb = (b * LTOK + l) * DIMC + head * 16;

        const float4* qg = (const float4*)(qkv + gb);
        const float4* kg = (const float4*)(qkv + MOFF + gb);
        const float4* vg = (const float4*)(qkv + 2 * MOFF + gb);
        float4 q4[4] = {qg[0], qg[1], qg[2], qg[3]};
        float4 k4[4] = {kg[0], kg[1], kg[2], kg[3]};
        float4 v4[4] = {vg[0], vg[1], vg[2], vg[3]};

#pragma unroll
        for (int i = 0; i < 4; ++i) {
            split_store(sm + SM_QH, sm + SM_QL, tt, 2*i,
                        q4[i].x * QSCALE, q4[i].y * QSCALE);
            split_store(sm + SM_QH, sm + SM_QL, tt, 2*i+1,
                        q4[i].z * QSCALE, q4[i].w * QSCALE);
            split_store(sm + SM_KH, sm + SM_KL, tt, 2*i,   k4[i].x, k4[i].y);
            split_store(sm + SM_KH, sm + SM_KL, tt, 2*i+1, k4[i].z, k4[i].w);
        }
        float vv[16] = {v4[0].x,v4[0].y,v4[0].z,v4[0].w, v4[1].x,v4[1].y,v4[1].z,v4[1].w,
                        v4[2].x,v4[2].y,v4[2].z,v4[2].w, v4[3].x,v4[3].y,v4[3].z,v4[3].w};
#pragma unroll
        for (int d = 0; d < 16; ++d) {
            uint32_t hp = pkf16(vv[d], 0.f);
            float lo = vv[d] - h2f_lo(hp);
            uint32_t lp = pkf16(lo, 0.f);
            *(unsigned short*)(sm + SM_VTH + d * 1040 + tt * 2) = (unsigned short)(hp & 0xFFFFu);
            *(unsigned short*)(sm + SM_VTL + d * 1040 + tt * 2) = (unsigned short)(lp & 0xFFFFu);
        }
    }
    // conv weights
    for (int i = tid; i < 16 * 125; i += 256) {
        int c = i / 125, tap = i % 125;
        wsm[i] = wconv[(head * 16 + c) * 125 + tap];
    }
    __syncthreads();

    // ================= LePE conv (registers + shuffles) =================
    // lane = H row (0..31); warp handles channels {2*warpid, 2*warpid+1}
    {
        float vr[2][16], co[2][16], bv[2];
#pragma unroll
        for (int c2 = 0; c2 < 2; ++c2) {
            int c  = warpid * 2 + c2;
            bv[c2] = __ldg(bias + head * 16 + c);
            int gb = (b * LTOK + lane * 1024 + (w_o * 4) * 32 + s_o * 4) * DIMC
                   + head * 16 + c;
#pragma unroll
            for (int j = 0; j < 16; ++j) {
                vr[c2][j] = __ldg(qkv + 2 * MOFF + gb + ((j >> 2) * 32 + (j & 3)) * DIMC);
                co[c2][j] = 0.f;
            }
        }
#pragma unroll
        for (int dh = 0; dh < 5; ++dh) {
            int hs = lane + dh - 2;
            bool ok = (unsigned)hs < 32u;
            int src = hs < 0 ? 0 : (hs > 31 ? 31 : hs);
            float tmp[2][16];
#pragma unroll
            for (int c2 = 0; c2 < 2; ++c2)
#pragma unroll
                for (int j = 0; j < 16; ++j)
                    tmp[c2][j] = __shfl_sync(0xFFFFFFFFu, vr[c2][j], src);
            if (ok) {
#pragma unroll
                for (int c2 = 0; c2 < 2; ++c2) {
                    const float* wc = wsm + (warpid * 2 + c2) * 125 + dh * 25;
#pragma unroll
                    for (int dw = 0; dw < 5; ++dw)
#pragma unroll
                        for (int ds = 0; ds < 5; ++ds) {
                            float wt = wc[dw * 5 + ds];
#pragma unroll
                            for (int w = 0; w < 4; ++w)
#pragma unroll
                                for (int s = 0; s < 4; ++s) {
                                    int ww = w + dw - 2, ss = s + ds - 2;
                                    if (ww >= 0 && ww < 4 && ss >= 0 && ss < 4)
                                        co[c2][w * 4 + s] += wt * tmp[c2][ww * 4 + ss];
                                }
                        }
                }
            }
        }
#pragma unroll
        for (int c2 = 0; c2 < 2; ++c2)
#pragma unroll
            for (int j = 0; j < 16; ++j)
                cbuf[(lane * 16 + j) * 20 + warpid * 2 + c2] = co[c2][j] + bv[c2];
    }
    __syncthreads();

    // ================= attention: per-warp 64 q-rows, flash loop =============
    // Q A-fragments (4 m-tiles x hi/lo)
    uint32_t qh[4][4], ql[4][4];
#pragma unroll
    for (int mt = 0; mt < 4; ++mt) {
        int r0 = warpid * 64 + mt * 16 + (lane >> 2);
        const char* qro = sm + SM_QH + r0 * 48 + (lane & 3) * 4;
        qh[mt][0] = *(const uint32_t*)qro;
        qh[mt][1] = *(const uint32_t*)(qro + 8 * 48);
        qh[mt][2] = *(const uint32_t*)(qro + 16);
        qh[mt][3] = *(const uint32_t*)(qro + 8 * 48 + 16);
        const char* qrl = sm + SM_QL + r0 * 48 + (lane & 3) * 4;
        ql[mt][0] = *(const uint32_t*)qrl;
        ql[mt][1] = *(const uint32_t*)(qrl + 8 * 48);
        ql[mt][2] = *(const uint32_t*)(qrl + 16);
        ql[mt][3] = *(const uint32_t*)(qrl + 8 * 48 + 16);
    }

    float o[4][2][4];
    float den[4][2];
#pragma unroll
    for (int mt = 0; mt < 4; ++mt) {
        den[mt][0] = den[mt][1] = 0.f;
#pragma unroll
        for (int nt = 0; nt < 2; ++nt)
#pragma unroll
            for (int j = 0; j < 4; ++j) o[mt][nt][j] = 0.f;
    }

    // K fragment cache (prefetched one chunk ahead): [nt][kh0,kh1,kl0,kl1]
    uint32_t kf[2][4];
#pragma unroll
    for (int nt = 0; nt < 2; ++nt) {
        int krow = nt * 8 + (lane >> 2);
        const char* kro = sm + SM_KH + krow * 48 + (lane & 3) * 4;
        const char* krl = sm + SM_KL + krow * 48 + (lane & 3) * 4;
        kf[nt][0] = *(const uint32_t*)kro;
        kf[nt][1] = *(const uint32_t*)(kro + 16);
        kf[nt][2] = *(const uint32_t*)krl;
        kf[nt][3] = *(const uint32_t*)(krl + 16);
    }

#pragma unroll 1
    for (int ch = 0; ch < 32; ++ch) {
        // ---- prefetch K frags for next chunk ----
        uint32_t kn[2][4];
        if (ch < 31) {
#pragma unroll
            for (int nt = 0; nt < 2; ++nt) {
                int krow = (ch + 1) * 16 + nt * 8 + (lane >> 2);
                const char* kro = sm + SM_KH + krow * 48 + (lane & 3) * 4;
                const char* krl = sm + SM_KL + krow * 48 + (lane & 3) * 4;
                kn[nt][0] = *(const uint32_t*)kro;
                kn[nt][1] = *(const uint32_t*)(kro + 16);
                kn[nt][2] = *(const uint32_t*)krl;
                kn[nt][3] = *(const uint32_t*)(krl + 16);
            }
        }

        // ---- S phase: scores for 16 keys, exp2, fp16 P frags ----
        uint32_t pah[4][4];
#pragma unroll
        for (int nt = 0; nt < 2; ++nt) {
#pragma unroll
            for (int mt = 0; mt < 4; ++mt) {
                // two independent accumulator chains: big term | small terms
                float sa[4] = {0.f, 0.f, 0.f, 0.f};
                float sb[4] = {0.f, 0.f, 0.f, 0.f};
                mma16816(sa, qh[mt], kf[nt][0], kf[nt][1]);   // qh*kh
                mma16816(sb, qh[mt], kf[nt][2], kf[nt][3]);   // qh*kl
                mma16816(sb, ql[mt], kf[nt][0], kf[nt][1]);   // ql*kh
                float p0 = ex2f(sa[0] + sb[0]);
                float p1 = ex2f(sa[1] + sb[1]);
                float p2 = ex2f(sa[2] + sb[2]);
                float p3 = ex2f(sa[3] + sb[3]);
                den[mt][0] += p0 + p1;
                den[mt][1] += p2 + p3;
                pah[mt][nt * 2 + 0] = pkf16(p0, p1);
                pah[mt][nt * 2 + 1] = pkf16(p2, p3);
            }
        }

        // ---- PV phase: O += Ph*Vh + Ph*Vl (Pl term dropped, ~2^-12 rel) ----
#pragma unroll
        for (int ntd = 0; ntd < 2; ++ntd) {
            int vrow = ntd * 8 + (lane >> 2);
            int kof  = ch * 16 + (lane & 3) * 2;
            const char* vh = sm + SM_VTH + vrow * 1040 + kof * 2;
            uint32_t vh0 = *(const uint32_t*)vh;
            uint32_t vh1 = *(const uint32_t*)(vh + 16);
            const char* vl = sm + SM_VTL + vrow * 1040 + kof * 2;
            uint32_t vl0 = *(const uint32_t*)vl;
            uint32_t vl1 = *(const uint32_t*)(vl + 16);
#pragma unroll
            for (int mt = 0; mt < 4; ++mt) {
                mma16816(o[mt][ntd], pah[mt], vh0, vh1);
                mma16816(o[mt][ntd], pah[mt], vl0, vl1);
            }
        }

        // rotate prefetched K frags in
        if (ch < 31) {
#pragma unroll
            for (int nt = 0; nt < 2; ++nt)
#pragma unroll
                for (int j = 0; j < 4; ++j) kf[nt][j] = kn[nt][j];
        }
    }

    // ================= output: normalize + conv + store =================
#pragma unroll
    for (int mt = 0; mt < 4; ++mt) {
#pragma unroll
        for (int rh = 0; rh < 2; ++rh) {
            float d = den[mt][rh];
            d += __shfl_xor_sync(0xFFFFFFFFu, d, 1);
            d += __shfl_xor_sync(0xFFFFFFFFu, d, 2);
            den[mt][rh] = d;
        }
#pragma unroll
        for (int rh = 0; rh < 2; ++rh) {
            int t = warpid * 64 + mt * 16 + (lane >> 2) + rh * 8;
            float inv = 1.0f / den[mt][rh];
            int hi = t >> 4, wi = (t >> 2) & 3, si = t & 3;
            int l  = hi * 1024 + (w_o * 4 + wi) * 32 + s_o * 4 + si;
            float* og = out + (size_t)(b * LTOK + l) * DIMC + head * 16;
#pragma unroll
            for (int ntd = 0; ntd < 2; ++ntd) {
                int dcol = ntd * 8 + (lane & 3) * 2;
                float c0 = o[mt][ntd][rh * 2 + 0] * inv + cbuf[t * 20 + dcol];
                float c1 = o[mt][ntd][rh * 2 + 1] * inv + cbuf[t * 20 + dcol + 1];
                *(float2*)(og + dcol) = make_float2(c0, c1);
            }
        }
    }
}

extern "C" void kernel_launch(void* const* d_in, const int* in_sizes, int n_in,
                              void* d_out, int out_size)
{
    (void)in_sizes; (void)n_in; (void)out_size;
    const float* qkv  = (const float*)d_in[0];
    const float* w    = (const float*)d_in[1];
    const float* bias = (const float*)d_in[2];
    float* out = (float*)d_out;

    cudaFuncSetAttribute(lepe_attn_hmma,
                         cudaFuncAttributeMaxDynamicSharedMemorySize, SMEM_TOTAL);
    lepe_attn_hmma<<<1024, 256, SMEM_TOTAL>>>(qkv, w, bias, out);
}

// round 14
// speedup vs baseline: 1.2720x; 1.1011x over previous
#include <cuda_runtime.h>
#include <cuda_fp16.h>
#include <cstdint>

#define DIMC   128
#define LTOK   32768
#define QSCALE (0.25f * 1.4426950408889634f)   // HD^-0.5 * log2(e)

// ---------------- smem byte offsets ----------------
// Qh/Ql/Kh/Kl: 512 rows x 32B (16 fp16), 16B-chunk XOR swizzle -> conflict-free frags
// VTh/VTl: V^T [16 d][520 keys] fp16 (1040B stride; 512 used)
// wsm: conv weights [16 c][125 taps] fp32
// cbuf (ALIASES Qh after Q-frag load): fp16x2 [8 ch-pairs][512 tokens]
#define SM_QH   0
#define SM_QL   16384
#define SM_KH   32768
#define SM_KL   49152
#define SM_VTH  65536
#define SM_VTL  82176
#define SM_WSM  98816
#define SM_CBUF SM_QH
#define SMEM_TOTAL 106816

// ---------------- helpers ----------------
__device__ __forceinline__ float ex2f(float x) {
    float y; asm("ex2.approx.f32 %0, %1;" : "=f"(y) : "f"(x)); return y;
}
// pack: low 16 bits = fp16(a), high 16 bits = fp16(b)
__device__ __forceinline__ uint32_t pkf16(float a, float b) {
    uint32_t r;
    asm("cvt.rn.f16x2.f32 %0, %1, %2;" : "=r"(r) : "f"(b), "f"(a));
    return r;
}
__device__ __forceinline__ float h2f_lo(uint32_t p) {
    return __half2float(__ushort_as_half((unsigned short)(p & 0xFFFFu)));
}
__device__ __forceinline__ float h2f_hi(uint32_t p) {
    return __half2float(__ushort_as_half((unsigned short)(p >> 16)));
}
// swizzled byte offset within a Q/K buffer: row r (0..511), u32 index i (0..7)
__device__ __forceinline__ uint32_t qk_off(int r, int i) {
    return (uint32_t)(r * 32 + ((((i >> 2) ^ (r >> 2)) & 1) << 4) + (i & 3) * 4);
}
// m16n8k16 row.col fp16 MMA, fp32 accumulate in-place
__device__ __forceinline__ void mma16816(float* c, const uint32_t* a,
                                          uint32_t b0, uint32_t b1) {
    asm volatile(
        "mma.sync.aligned.m16n8k16.row.col.f32.f16.f16.f32 "
        "{%0,%1,%2,%3}, {%4,%5,%6,%7}, {%8,%9}, {%0,%1,%2,%3};"
        : "+f"(c[0]), "+f"(c[1]), "+f"(c[2]), "+f"(c[3])
        : "r"(a[0]), "r"(a[1]), "r"(a[2]), "r"(a[3]), "r"(b0), "r"(b1));
}
// split fp32 pair -> hi/lo fp16x2, swizzled store into Q/K buffers
__device__ __forceinline__ void split_store_sw(char* hib, char* lob, int row, int i,
                                               float a, float b) {
    uint32_t hp = pkf16(a, b);
    float r0 = a - h2f_lo(hp);
    float r1 = b - h2f_hi(hp);
    uint32_t lp = pkf16(r0, r1);
    uint32_t off = qk_off(row, i);
    *(uint32_t*)(hib + off) = hp;
    *(uint32_t*)(lob + off) = lp;
}

// =============================== kernel ====================================
__global__ void __launch_bounds__(256, 2)
lepe_attn_hmma(const float* __restrict__ qkv,
               const float* __restrict__ wconv,
               const float* __restrict__ bias,
               float* __restrict__ out)
{
    extern __shared__ char sm[];
    float* wsm = (float*)(sm + SM_WSM);

    const int tid    = threadIdx.x;
    const int warpid = tid >> 5;          // 0..7
    const int lane   = tid & 31;

    const int wh   = blockIdx.x;          // 1024 = 128 windows * 8 heads
    const int head = wh & 7;
    const int win  = wh >> 3;
    const int b    = win >> 6;
    const int w_o  = (win >> 3) & 7;
    const int s_o  = win & 7;
    const int MOFF = 2 * LTOK * DIMC;

    // ================= prologue: convert Q/K/V to split-fp16 =================
#pragma unroll
    for (int tk = 0; tk < 2; ++tk) {
        const int tt = tid + tk * 256;                 // token 0..511
        const int hi = tt >> 4, wi = (tt >> 2) & 3, si = tt & 3;
        const int l  = hi * 1024 + (w_o * 4 + wi) * 32 + s_o * 4 + si;
        const int gb = (b * LTOK + l) * DIMC + head * 16;

        const float4* qg = (const float4*)(qkv + gb);
        const float4* kg = (const float4*)(qkv + MOFF + gb);
        const float4* vg = (const float4*)(qkv + 2 * MOFF + gb);
        float4 q4[4] = {qg[0], qg[1], qg[2], qg[3]};
        float4 k4[4] = {kg[0], kg[1], kg[2], kg[3]};
        float4 v4[4] = {vg[0], vg[1], vg[2], vg[3]};

#pragma unroll
        for (int i = 0; i < 4; ++i) {
            split_store_sw(sm + SM_QH, sm + SM_QL, tt, 2*i,
                           q4[i].x * QSCALE, q4[i].y * QSCALE);
            split_store_sw(sm + SM_QH, sm + SM_QL, tt, 2*i+1,
                           q4[i].z * QSCALE, q4[i].w * QSCALE);
            split_store_sw(sm + SM_KH, sm + SM_KL, tt, 2*i,   k4[i].x, k4[i].y);
            split_store_sw(sm + SM_KH, sm + SM_KL, tt, 2*i+1, k4[i].z, k4[i].w);
        }
        float vv[16] = {v4[0].x,v4[0].y,v4[0].z,v4[0].w, v4[1].x,v4[1].y,v4[1].z,v4[1].w,
                        v4[2].x,v4[2].y,v4[2].z,v4[2].w, v4[3].x,v4[3].y,v4[3].z,v4[3].w};
#pragma unroll
        for (int d = 0; d < 16; ++d) {
            uint32_t hp = pkf16(vv[d], 0.f);
            float lo = vv[d] - h2f_lo(hp);
            uint32_t lp = pkf16(lo, 0.f);
            *(unsigned short*)(sm + SM_VTH + d * 1040 + tt * 2) = (unsigned short)(hp & 0xFFFFu);
            *(unsigned short*)(sm + SM_VTL + d * 1040 + tt * 2) = (unsigned short)(lp & 0xFFFFu);
        }
    }
    // conv weights
    for (int i = tid; i < 16 * 125; i += 256) {
        int c = i / 125, tap = i % 125;
        wsm[i] = wconv[(head * 16 + c) * 125 + tap];
    }
    __syncthreads();

    // ================= Q fragments FIRST (Qh/Ql smem dies after this) ========
    uint32_t qh[4][4], ql[4][4];
    {
        const int c = lane & 3;
#pragma unroll
        for (int mt = 0; mt < 4; ++mt) {
            int r0 = warpid * 64 + mt * 16 + (lane >> 2);
            qh[mt][0] = *(const uint32_t*)(sm + SM_QH + qk_off(r0,     c));
            qh[mt][1] = *(const uint32_t*)(sm + SM_QH + qk_off(r0 + 8, c));
            qh[mt][2] = *(const uint32_t*)(sm + SM_QH + qk_off(r0,     4 + c));
            qh[mt][3] = *(const uint32_t*)(sm + SM_QH + qk_off(r0 + 8, 4 + c));
            ql[mt][0] = *(const uint32_t*)(sm + SM_QL + qk_off(r0,     c));
            ql[mt][1] = *(const uint32_t*)(sm + SM_QL + qk_off(r0 + 8, c));
            ql[mt][2] = *(const uint32_t*)(sm + SM_QL + qk_off(r0,     4 + c));
            ql[mt][3] = *(const uint32_t*)(sm + SM_QL + qk_off(r0 + 8, 4 + c));
        }
    }
    __syncthreads();   // all Q reads done before cbuf overwrites Qh

    // ================= LePE conv (registers + shuffles), writes cbuf =========
    // lane = H row (0..31); warp handles channel pair {2*warpid, 2*warpid+1}
    {
        float co[2][16], bv[2];
        bv[0] = __ldg(bias + head * 16 + warpid * 2);
        bv[1] = __ldg(bias + head * 16 + warpid * 2 + 1);
#pragma unroll
        for (int c2 = 0; c2 < 2; ++c2) {
            const int c = warpid * 2 + c2;
            float vr[16];
            int gb = (b * LTOK + lane * 1024 + (w_o * 4) * 32 + s_o * 4) * DIMC
                   + head * 16 + c;
#pragma unroll
            for (int j = 0; j < 16; ++j) {
                vr[j] = __ldg(qkv + 2 * MOFF + gb + ((j >> 2) * 32 + (j & 3)) * DIMC);
                co[c2][j] = 0.f;
            }
#pragma unroll
            for (int dh = 0; dh < 5; ++dh) {
                int hs = lane + dh - 2;
                bool ok = (unsigned)hs < 32u;
                int src = hs < 0 ? 0 : (hs > 31 ? 31 : hs);
                float tmp[16];
#pragma unroll
                for (int j = 0; j < 16; ++j)
                    tmp[j] = __shfl_sync(0xFFFFFFFFu, vr[j], src);
                if (ok) {
                    const float* wc = wsm + c * 125 + dh * 25;
#pragma unroll
                    for (int dw = 0; dw < 5; ++dw)
#pragma unroll
                        for (int ds = 0; ds < 5; ++ds) {
                            float wt = wc[dw * 5 + ds];
#pragma unroll
                            for (int w = 0; w < 4; ++w)
#pragma unroll
                                for (int s = 0; s < 4; ++s) {
                                    int ww = w + dw - 2, ss = s + ds - 2;
                                    if (ww >= 0 && ww < 4 && ss >= 0 && ss < 4)
                                        co[c2][w * 4 + s] += wt * tmp[ww * 4 + ss];
                                }
                        }
                }
            }
        }
        // packed fp16x2 store: cbuf[pair=warpid][token]
#pragma unroll
        for (int j = 0; j < 16; ++j) {
            uint32_t pk = pkf16(co[0][j] + bv[0], co[1][j] + bv[1]);
            *(uint32_t*)(sm + SM_CBUF + warpid * 2048 + (lane * 16 + j) * 4) = pk;
        }
    }
    __syncthreads();

    // ================= attention: per-warp 64 q-rows, flash loop =============
    float o[4][2][4];
    float den[4][2];
#pragma unroll
    for (int mt = 0; mt < 4; ++mt) {
        den[mt][0] = den[mt][1] = 0.f;
#pragma unroll
        for (int nt = 0; nt < 2; ++nt)
#pragma unroll
            for (int j = 0; j < 4; ++j) o[mt][nt][j] = 0.f;
    }

    const int fc = lane & 3;

#pragma unroll 1
    for (int ch = 0; ch < 32; ++ch) {
        // ---- S phase: scores for 16 keys, exp2, fp16 P frags ----
        uint32_t pah[4][4];
#pragma unroll
        for (int nt = 0; nt < 2; ++nt) {
            int krow = ch * 16 + nt * 8 + (lane >> 2);
            uint32_t kh0 = *(const uint32_t*)(sm + SM_KH + qk_off(krow, fc));
            uint32_t kh1 = *(const uint32_t*)(sm + SM_KH + qk_off(krow, 4 + fc));
            uint32_t kl0 = *(const uint32_t*)(sm + SM_KL + qk_off(krow, fc));
            uint32_t kl1 = *(const uint32_t*)(sm + SM_KL + qk_off(krow, 4 + fc));
#pragma unroll
            for (int mt = 0; mt < 4; ++mt) {
                // two independent accumulator chains: big term | small terms
                float sa[4] = {0.f, 0.f, 0.f, 0.f};
                float sb[4] = {0.f, 0.f, 0.f, 0.f};
                mma16816(sa, qh[mt], kh0, kh1);   // qh*kh
                mma16816(sb, qh[mt], kl0, kl1);   // qh*kl
                mma16816(sb, ql[mt], kh0, kh1);   // ql*kh
                float p0 = ex2f(sa[0] + sb[0]);
                float p1 = ex2f(sa[1] + sb[1]);
                float p2 = ex2f(sa[2] + sb[2]);
                float p3 = ex2f(sa[3] + sb[3]);
                den[mt][0] += p0 + p1;
                den[mt][1] += p2 + p3;
                pah[mt][nt * 2 + 0] = pkf16(p0, p1);
                pah[mt][nt * 2 + 1] = pkf16(p2, p3);
            }
        }

        // ---- PV phase: O += Ph*Vh + Ph*Vl (Pl term dropped, ~2^-12 rel) ----
#pragma unroll
        for (int ntd = 0; ntd < 2; ++ntd) {
            int vrow = ntd * 8 + (lane >> 2);
            int kof  = ch * 16 + fc * 2;
            const char* vh = sm + SM_VTH + vrow * 1040 + kof * 2;
            uint32_t vh0 = *(const uint32_t*)vh;
            uint32_t vh1 = *(const uint32_t*)(vh + 16);
            const char* vl = sm + SM_VTL + vrow * 1040 + kof * 2;
            uint32_t vl0 = *(const uint32_t*)vl;
            uint32_t vl1 = *(const uint32_t*)(vl + 16);
#pragma unroll
            for (int mt = 0; mt < 4; ++mt) {
                mma16816(o[mt][ntd], pah[mt], vh0, vh1);
                mma16816(o[mt][ntd], pah[mt], vl0, vl1);
            }
        }
    }

    // ================= output: normalize + conv + store =================
#pragma unroll
    for (int mt = 0; mt < 4; ++mt) {
#pragma unroll
        for (int rh = 0; rh < 2; ++rh) {
            float d = den[mt][rh];
            d += __shfl_xor_sync(0xFFFFFFFFu, d, 1);
            d += __shfl_xor_sync(0xFFFFFFFFu, d, 2);
            den[mt][rh] = d;
        }
#pragma unroll
        for (int rh = 0; rh < 2; ++rh) {
            int t = warpid * 64 + mt * 16 + (lane >> 2) + rh * 8;
            float inv = 1.0f / den[mt][rh];
            int hi = t >> 4, wi = (t >> 2) & 3, si = t & 3;
            int l  = hi * 1024 + (w_o * 4 + wi) * 32 + s_o * 4 + si;
            float* og = out + (size_t)(b * LTOK + l) * DIMC + head * 16;
#pragma unroll
            for (int ntd = 0; ntd < 2; ++ntd) {
                int dcol = ntd * 8 + fc * 2;
                uint32_t cp = *(const uint32_t*)(sm + SM_CBUF
                                + (ntd * 4 + fc) * 2048 + t * 4);
                float c0 = o[mt][ntd][rh * 2 + 0] * inv + h2f_lo(cp);
                float c1 = o[mt][ntd][rh * 2 + 1] * inv + h2f_hi(cp);
                *(float2*)(og + dcol) = make_float2(c0, c1);
            }
        }
    }
}

extern "C" void kernel_launch(void* const* d_in, const int* in_sizes, int n_in,
                              void* d_out, int out_size)
{
    (void)in_sizes; (void)n_in; (void)out_size;
    const float* qkv  = (const float*)d_in[0];
    const float* w    = (const float*)d_in[1];
    const float* bias = (const float*)d_in[2];
    float* out = (float*)d_out;

    cudaFuncSetAttribute(lepe_attn_hmma,
                         cudaFuncAttributeMaxDynamicSharedMemorySize, SMEM_TOTAL);
    lepe_attn_hmma<<<1024, 256, SMEM_TOTAL>>>(qkv, w, bias, out);
}

// round 15
// speedup vs baseline: 1.3814x; 1.0860x over previous
#include <cuda_runtime.h>
#include <cuda_fp16.h>
#include <cstdint>

#define DIMC   128
#define LTOK   32768
#define QSCALE (0.25f * 1.4426950408889634f)   // HD^-0.5 * log2(e)
#define ONESF16X2 0x3C003C00u                  // (1.0h, 1.0h)

// ---------------- smem byte offsets ----------------
// Qh/Ql/Kh/Kl: 512 rows x 32B (16 fp16), 16B-chunk XOR swizzle -> conflict-free frags
// VTh/VTl: V^T [16 d][520 keys] fp16 (1040B stride; 512 used)
// wsm: conv weights [16 c][125 taps] fp32
// cbuf (ALIASES Qh after Q-frag load): fp16x2 [8 ch-pairs][512 tokens]
#define SM_QH   0
#define SM_QL   16384
#define SM_KH   32768
#define SM_KL   49152
#define SM_VTH  65536
#define SM_VTL  82176
#define SM_WSM  98816
#define SM_CBUF SM_QH
#define SMEM_TOTAL 106816

// ---------------- helpers ----------------
// pack: low 16 bits = fp16(a), high 16 bits = fp16(b)
__device__ __forceinline__ uint32_t pkf16(float a, float b) {
    uint32_t r;
    asm("cvt.rn.f16x2.f32 %0, %1, %2;" : "=r"(r) : "f"(b), "f"(a));
    return r;
}
__device__ __forceinline__ uint32_t ex2h2(uint32_t s) {
    uint32_t r;
    asm("ex2.approx.f16x2 %0, %1;" : "=r"(r) : "r"(s));
    return r;
}
__device__ __forceinline__ float h2f_lo(uint32_t p) {
    return __half2float(__ushort_as_half((unsigned short)(p & 0xFFFFu)));
}
__device__ __forceinline__ float h2f_hi(uint32_t p) {
    return __half2float(__ushort_as_half((unsigned short)(p >> 16)));
}
// swizzled byte offset within a Q/K buffer: row r (0..511), u32 index i (0..7)
__device__ __forceinline__ uint32_t qk_off(int r, int i) {
    return (uint32_t)(r * 32 + ((((i >> 2) ^ (r >> 2)) & 1) << 4) + (i & 3) * 4);
}
// m16n8k16 row.col fp16 MMA, fp32 accumulate in-place
__device__ __forceinline__ void mma16816(float* c, const uint32_t* a,
                                          uint32_t b0, uint32_t b1) {
    asm volatile(
        "mma.sync.aligned.m16n8k16.row.col.f32.f16.f16.f32 "
        "{%0,%1,%2,%3}, {%4,%5,%6,%7}, {%8,%9}, {%0,%1,%2,%3};"
        : "+f"(c[0]), "+f"(c[1]), "+f"(c[2]), "+f"(c[3])
        : "r"(a[0]), "r"(a[1]), "r"(a[2]), "r"(a[3]), "r"(b0), "r"(b1));
}
// split fp32 pair -> hi/lo fp16x2, swizzled store into Q/K buffers
__device__ __forceinline__ void split_store_sw(char* hib, char* lob, int row, int i,
                                               float a, float b) {
    uint32_t hp = pkf16(a, b);
    float r0 = a - h2f_lo(hp);
    float r1 = b - h2f_hi(hp);
    uint32_t lp = pkf16(r0, r1);
    uint32_t off = qk_off(row, i);
    *(uint32_t*)(hib + off) = hp;
    *(uint32_t*)(lob + off) = lp;
}

// =============================== kernel ====================================
__global__ void __launch_bounds__(256, 2)
lepe_attn_hmma(const float* __restrict__ qkv,
               const float* __restrict__ wconv,
               const float* __restrict__ bias,
               float* __restrict__ out)
{
    extern __shared__ char sm[];
    float* wsm = (float*)(sm + SM_WSM);

    const int tid    = threadIdx.x;
    const int warpid = tid >> 5;          // 0..7
    const int lane   = tid & 31;

    const int wh   = blockIdx.x;          // 1024 = 128 windows * 8 heads
    const int head = wh & 7;
    const int win  = wh >> 3;
    const int b    = win >> 6;
    const int w_o  = (win >> 3) & 7;
    const int s_o  = win & 7;
    const int MOFF = 2 * LTOK * DIMC;

    // ================= prologue: convert Q/K/V to split-fp16 =================
#pragma unroll
    for (int tk = 0; tk < 2; ++tk) {
        const int tt = tid + tk * 256;                 // token 0..511
        const int hi = tt >> 4, wi = (tt >> 2) & 3, si = tt & 3;
        const int l  = hi * 1024 + (w_o * 4 + wi) * 32 + s_o * 4 + si;
        const int gb = (b * LTOK + l) * DIMC + head * 16;

        const float4* qg = (const float4*)(qkv + gb);
        const float4* kg = (const float4*)(qkv + MOFF + gb);
        const float4* vg = (const float4*)(qkv + 2 * MOFF + gb);
        float4 q4[4] = {qg[0], qg[1], qg[2], qg[3]};
        float4 k4[4] = {kg[0], kg[1], kg[2], kg[3]};
        float4 v4[4] = {vg[0], vg[1], vg[2], vg[3]};

#pragma unroll
        for (int i = 0; i < 4; ++i) {
            split_store_sw(sm + SM_QH, sm + SM_QL, tt, 2*i,
                           q4[i].x * QSCALE, q4[i].y * QSCALE);
            split_store_sw(sm + SM_QH, sm + SM_QL, tt, 2*i+1,
                           q4[i].z * QSCALE, q4[i].w * QSCALE);
            split_store_sw(sm + SM_KH, sm + SM_KL, tt, 2*i,   k4[i].x, k4[i].y);
            split_store_sw(sm + SM_KH, sm + SM_KL, tt, 2*i+1, k4[i].z, k4[i].w);
        }
        float vv[16] = {v4[0].x,v4[0].y,v4[0].z,v4[0].w, v4[1].x,v4[1].y,v4[1].z,v4[1].w,
                        v4[2].x,v4[2].y,v4[2].z,v4[2].w, v4[3].x,v4[3].y,v4[3].z,v4[3].w};
#pragma unroll
        for (int d = 0; d < 16; ++d) {
            uint32_t hp = pkf16(vv[d], 0.f);
            float lo = vv[d] - h2f_lo(hp);
            uint32_t lp = pkf16(lo, 0.f);
            *(unsigned short*)(sm + SM_VTH + d * 1040 + tt * 2) = (unsigned short)(hp & 0xFFFFu);
            *(unsigned short*)(sm + SM_VTL + d * 1040 + tt * 2) = (unsigned short)(lp & 0xFFFFu);
        }
    }
    // conv weights
    for (int i = tid; i < 16 * 125; i += 256) {
        int c = i / 125, tap = i % 125;
        wsm[i] = wconv[(head * 16 + c) * 125 + tap];
    }
    __syncthreads();

    // ================= Q fragments FIRST (Qh/Ql smem dies after this) ========
    uint32_t qh[4][4], ql[4][4];
    {
        const int c = lane & 3;
#pragma unroll
        for (int mt = 0; mt < 4; ++mt) {
            int r0 = warpid * 64 + mt * 16 + (lane >> 2);
            qh[mt][0] = *(const uint32_t*)(sm + SM_QH + qk_off(r0,     c));
            qh[mt][1] = *(const uint32_t*)(sm + SM_QH + qk_off(r0 + 8, c));
            qh[mt][2] = *(const uint32_t*)(sm + SM_QH + qk_off(r0,     4 + c));
            qh[mt][3] = *(const uint32_t*)(sm + SM_QH + qk_off(r0 + 8, 4 + c));
            ql[mt][0] = *(const uint32_t*)(sm + SM_QL + qk_off(r0,     c));
            ql[mt][1] = *(const uint32_t*)(sm + SM_QL + qk_off(r0 + 8, c));
            ql[mt][2] = *(const uint32_t*)(sm + SM_QL + qk_off(r0,     4 + c));
            ql[mt][3] = *(const uint32_t*)(sm + SM_QL + qk_off(r0 + 8, 4 + c));
        }
    }
    __syncthreads();   // all Q reads done before cbuf overwrites Qh

    // ================= LePE conv (registers + shuffles), writes cbuf =========
    // lane = H row (0..31); warp handles channel pair {2*warpid, 2*warpid+1}
    {
        float co[2][16], bv[2];
        bv[0] = __ldg(bias + head * 16 + warpid * 2);
        bv[1] = __ldg(bias + head * 16 + warpid * 2 + 1);
#pragma unroll
        for (int c2 = 0; c2 < 2; ++c2) {
            const int c = warpid * 2 + c2;
            float vr[16];
            int gb = (b * LTOK + lane * 1024 + (w_o * 4) * 32 + s_o * 4) * DIMC
                   + head * 16 + c;
#pragma unroll
            for (int j = 0; j < 16; ++j) {
                vr[j] = __ldg(qkv + 2 * MOFF + gb + ((j >> 2) * 32 + (j & 3)) * DIMC);
                co[c2][j] = 0.f;
            }
#pragma unroll
            for (int dh = 0; dh < 5; ++dh) {
                int hs = lane + dh - 2;
                bool ok = (unsigned)hs < 32u;
                int src = hs < 0 ? 0 : (hs > 31 ? 31 : hs);
                float tmp[16];
#pragma unroll
                for (int j = 0; j < 16; ++j)
                    tmp[j] = __shfl_sync(0xFFFFFFFFu, vr[j], src);
                if (ok) {
                    const float* wc = wsm + c * 125 + dh * 25;
#pragma unroll
                    for (int dw = 0; dw < 5; ++dw)
#pragma unroll
                        for (int ds = 0; ds < 5; ++ds) {
                            float wt = wc[dw * 5 + ds];
#pragma unroll
                            for (int w = 0; w < 4; ++w)
#pragma unroll
                                for (int s = 0; s < 4; ++s) {
                                    int ww = w + dw - 2, ss = s + ds - 2;
                                    if (ww >= 0 && ww < 4 && ss >= 0 && ss < 4)
                                        co[c2][w * 4 + s] += wt * tmp[ww * 4 + ss];
                                }
                        }
                }
            }
        }
        // packed fp16x2 store: cbuf[pair=warpid][token]
#pragma unroll
        for (int j = 0; j < 16; ++j) {
            uint32_t pk = pkf16(co[0][j] + bv[0], co[1][j] + bv[1]);
            *(uint32_t*)(sm + SM_CBUF + warpid * 2048 + (lane * 16 + j) * 4) = pk;
        }
    }
    __syncthreads();

    // ================= attention: per-warp 64 q-rows, flash loop =============
    float o[4][2][4];
    float dn[4][4];     // ones-MMA denominator accumulators (cols identical)
#pragma unroll
    for (int mt = 0; mt < 4; ++mt) {
#pragma unroll
        for (int j = 0; j < 4; ++j) dn[mt][j] = 0.f;
#pragma unroll
        for (int nt = 0; nt < 2; ++nt)
#pragma unroll
            for (int j = 0; j < 4; ++j) o[mt][nt][j] = 0.f;
    }

    const int fc = lane & 3;

#pragma unroll 1
    for (int ch = 0; ch < 32; ++ch) {
        // ---- S phase: scores for 16 keys -> fp16 -> ex2.f16x2 -> P frags ----
        uint32_t pah[4][4];
#pragma unroll
        for (int nt = 0; nt < 2; ++nt) {
            int krow = ch * 16 + nt * 8 + (lane >> 2);
            uint32_t kh0 = *(const uint32_t*)(sm + SM_KH + qk_off(krow, fc));
            uint32_t kh1 = *(const uint32_t*)(sm + SM_KH + qk_off(krow, 4 + fc));
            uint32_t kl0 = *(const uint32_t*)(sm + SM_KL + qk_off(krow, fc));
            uint32_t kl1 = *(const uint32_t*)(sm + SM_KL + qk_off(krow, 4 + fc));
#pragma unroll
            for (int mt = 0; mt < 4; ++mt) {
                float s[4] = {0.f, 0.f, 0.f, 0.f};
                mma16816(s, qh[mt], kh0, kh1);   // qh*kh
                mma16816(s, qh[mt], kl0, kl1);   // qh*kl
                mma16816(s, ql[mt], kh0, kh1);   // ql*kh
                pah[mt][nt * 2 + 0] = ex2h2(pkf16(s[0], s[1]));
                pah[mt][nt * 2 + 1] = ex2h2(pkf16(s[2], s[3]));
            }
        }

        // ---- PV phase: O += Ph*Vh + Ph*Vl ; den += Ph*ones (tensor pipe) ----
#pragma unroll
        for (int ntd = 0; ntd < 2; ++ntd) {
            int vrow = ntd * 8 + (lane >> 2);
            int kof  = ch * 16 + fc * 2;
            const char* vh = sm + SM_VTH + vrow * 1040 + kof * 2;
            uint32_t vh0 = *(const uint32_t*)vh;
            uint32_t vh1 = *(const uint32_t*)(vh + 16);
            const char* vl = sm + SM_VTL + vrow * 1040 + kof * 2;
            uint32_t vl0 = *(const uint32_t*)vl;
            uint32_t vl1 = *(const uint32_t*)(vl + 16);
#pragma unroll
            for (int mt = 0; mt < 4; ++mt) {
                mma16816(o[mt][ntd], pah[mt], vh0, vh1);
                mma16816(o[mt][ntd], pah[mt], vl0, vl1);
            }
        }
#pragma unroll
        for (int mt = 0; mt < 4; ++mt)
            mma16816(dn[mt], pah[mt], ONESF16X2, ONESF16X2);
    }

    // ================= output: normalize + conv + store =================
#pragma unroll
    for (int mt = 0; mt < 4; ++mt) {
#pragma unroll
        for (int rh = 0; rh < 2; ++rh) {
            int t = warpid * 64 + mt * 16 + (lane >> 2) + rh * 8;
            float inv = 1.0f / dn[mt][rh * 2];   // row-sum; cols identical
            int hi = t >> 4, wi = (t >> 2) & 3, si = t & 3;
            int l  = hi * 1024 + (w_o * 4 + wi) * 32 + s_o * 4 + si;
            float* og = out + (size_t)(b * LTOK + l) * DIMC + head * 16;
#pragma unroll
            for (int ntd = 0; ntd < 2; ++ntd) {
                int dcol = ntd * 8 + fc * 2;
                uint32_t cp = *(const uint32_t*)(sm + SM_CBUF
                                + (ntd * 4 + fc) * 2048 + t * 4);
                float c0 = o[mt][ntd][rh * 2 + 0] * inv + h2f_lo(cp);
                float c1 = o[mt][ntd][rh * 2 + 1] * inv + h2f_hi(cp);
                *(float2*)(og + dcol) = make_float2(c0, c1);
            }
        }
    }
}

extern "C" void kernel_launch(void* const* d_in, const int* in_sizes, int n_in,
                              void* d_out, int out_size)
{
    (void)in_sizes; (void)n_in; (void)out_size;
    const float* qkv  = (const float*)d_in[0];
    const float* w    = (const float*)d_in[1];
    const float* bias = (const float*)d_in[2];
    float* out = (float*)d_out;

    cudaFuncSetAttribute(lepe_attn_hmma,
                         cudaFuncAttributeMaxDynamicSharedMemorySize, SMEM_TOTAL);
    lepe_attn_hmma<<<1024, 256, SMEM_TOTAL>>>(qkv, w, bias, out);
}

// round 16
// speedup vs baseline: 1.8101x; 1.3103x over previous
#include <cuda_runtime.h>
#include <cuda_fp16.h>
#include <cstdint>

#define DIMC   128
#define LTOK   32768
#define QSCALE (0.25f * 1.4426950408889634f)   // HD^-0.5 * log2(e)
#define ONESF16X2 0x3C003C00u                  // (1.0h, 1.0h)

// ---------------- smem byte offsets ----------------
// Qh/Kh: 512 rows x 32B (16 fp16), 16B-chunk XOR swizzle -> conflict-free frags
// VTh/VTl: V^T [16 d][520 keys] fp16 (1040B stride; 512 used)
// wsm: conv weights [16 c][125 taps] fp32
// cbuf (ALIASES Qh after Q-frag load): fp16x2 [8 ch-pairs][512 tokens]
#define SM_QH   0
#define SM_KH   16384
#define SM_VTH  32768
#define SM_VTL  49408
#define SM_WSM  66048
#define SM_CBUF SM_QH
#define SMEM_TOTAL 74048

// ---------------- helpers ----------------
// pack: low 16 bits = fp16(a), high 16 bits = fp16(b)
__device__ __forceinline__ uint32_t pkf16(float a, float b) {
    uint32_t r;
    asm("cvt.rn.f16x2.f32 %0, %1, %2;" : "=r"(r) : "f"(b), "f"(a));
    return r;
}
__device__ __forceinline__ uint32_t ex2h2(uint32_t s) {
    uint32_t r;
    asm("ex2.approx.f16x2 %0, %1;" : "=r"(r) : "r"(s));
    return r;
}
__device__ __forceinline__ float h2f_lo(uint32_t p) {
    return __half2float(__ushort_as_half((unsigned short)(p & 0xFFFFu)));
}
__device__ __forceinline__ float h2f_hi(uint32_t p) {
    return __half2float(__ushort_as_half((unsigned short)(p >> 16)));
}
// swizzled byte offset within a Q/K buffer: row r (0..511), u32 index i (0..7)
__device__ __forceinline__ uint32_t qk_off(int r, int i) {
    return (uint32_t)(r * 32 + ((((i >> 2) ^ (r >> 2)) & 1) << 4) + (i & 3) * 4);
}
// m16n8k16 row.col fp16 MMA, fp32 accumulate in-place
__device__ __forceinline__ void mma16816(float* c, const uint32_t* a,
                                          uint32_t b0, uint32_t b1) {
    asm volatile(
        "mma.sync.aligned.m16n8k16.row.col.f32.f16.f16.f32 "
        "{%0,%1,%2,%3}, {%4,%5,%6,%7}, {%8,%9}, {%0,%1,%2,%3};"
        : "+f"(c[0]), "+f"(c[1]), "+f"(c[2]), "+f"(c[3])
        : "r"(a[0]), "r"(a[1]), "r"(a[2]), "r"(a[3]), "r"(b0), "r"(b1));
}

// =============================== kernel ====================================
__global__ void __launch_bounds__(256, 2)
lepe_attn_hmma(const float* __restrict__ qkv,
               const float* __restrict__ wconv,
               const float* __restrict__ bias,
               float* __restrict__ out)
{
    extern __shared__ char sm[];
    float* wsm = (float*)(sm + SM_WSM);

    const int tid    = threadIdx.x;
    const int warpid = tid >> 5;          // 0..7
    const int lane   = tid & 31;

    const int wh   = blockIdx.x;          // 1024 = 128 windows * 8 heads
    const int head = wh & 7;
    const int win  = wh >> 3;
    const int b    = win >> 6;
    const int w_o  = (win >> 3) & 7;
    const int s_o  = win & 7;
    const int MOFF = 2 * LTOK * DIMC;

    // ================= prologue: convert Q/K/V to fp16 =======================
#pragma unroll
    for (int tk = 0; tk < 2; ++tk) {
        const int tt = tid + tk * 256;                 // token 0..511
        const int hi = tt >> 4, wi = (tt >> 2) & 3, si = tt & 3;
        const int l  = hi * 1024 + (w_o * 4 + wi) * 32 + s_o * 4 + si;
        const int gb = (b * LTOK + l) * DIMC + head * 16;

        const float4* qg = (const float4*)(qkv + gb);
        const float4* kg = (const float4*)(qkv + MOFF + gb);
        const float4* vg = (const float4*)(qkv + 2 * MOFF + gb);
        float4 q4[4] = {qg[0], qg[1], qg[2], qg[3]};
        float4 k4[4] = {kg[0], kg[1], kg[2], kg[3]};
        float4 v4[4] = {vg[0], vg[1], vg[2], vg[3]};

#pragma unroll
        for (int i = 0; i < 4; ++i) {
            *(uint32_t*)(sm + SM_QH + qk_off(tt, 2*i)) =
                pkf16(q4[i].x * QSCALE, q4[i].y * QSCALE);
            *(uint32_t*)(sm + SM_QH + qk_off(tt, 2*i+1)) =
                pkf16(q4[i].z * QSCALE, q4[i].w * QSCALE);
            *(uint32_t*)(sm + SM_KH + qk_off(tt, 2*i))   = pkf16(k4[i].x, k4[i].y);
            *(uint32_t*)(sm + SM_KH + qk_off(tt, 2*i+1)) = pkf16(k4[i].z, k4[i].w);
        }
        float vv[16] = {v4[0].x,v4[0].y,v4[0].z,v4[0].w, v4[1].x,v4[1].y,v4[1].z,v4[1].w,
                        v4[2].x,v4[2].y,v4[2].z,v4[2].w, v4[3].x,v4[3].y,v4[3].z,v4[3].w};
#pragma unroll
        for (int d = 0; d < 16; ++d) {
            uint32_t hp = pkf16(vv[d], 0.f);
            float lo = vv[d] - h2f_lo(hp);
            uint32_t lp = pkf16(lo, 0.f);
            *(unsigned short*)(sm + SM_VTH + d * 1040 + tt * 2) = (unsigned short)(hp & 0xFFFFu);
            *(unsigned short*)(sm + SM_VTL + d * 1040 + tt * 2) = (unsigned short)(lp & 0xFFFFu);
        }
    }
    // conv weights
    for (int i = tid; i < 16 * 125; i += 256) {
        int c = i / 125, tap = i % 125;
        wsm[i] = wconv[(head * 16 + c) * 125 + tap];
    }
    __syncthreads();

    // ================= Q fragments FIRST (Qh smem dies after this) ===========
    uint32_t qh[4][4];
    {
        const int c = lane & 3;
#pragma unroll
        for (int mt = 0; mt < 4; ++mt) {
            int r0 = warpid * 64 + mt * 16 + (lane >> 2);
            qh[mt][0] = *(const uint32_t*)(sm + SM_QH + qk_off(r0,     c));
            qh[mt][1] = *(const uint32_t*)(sm + SM_QH + qk_off(r0 + 8, c));
            qh[mt][2] = *(const uint32_t*)(sm + SM_QH + qk_off(r0,     4 + c));
            qh[mt][3] = *(const uint32_t*)(sm + SM_QH + qk_off(r0 + 8, 4 + c));
        }
    }
    __syncthreads();   // all Q reads done before cbuf overwrites Qh

    // ================= LePE conv (registers + shuffles), writes cbuf =========
    // lane = H row (0..31); warp handles channel pair {2*warpid, 2*warpid+1}
    {
        float co[2][16], bv[2];
        bv[0] = __ldg(bias + head * 16 + warpid * 2);
        bv[1] = __ldg(bias + head * 16 + warpid * 2 + 1);
#pragma unroll
        for (int c2 = 0; c2 < 2; ++c2) {
            const int c = warpid * 2 + c2;
            float vr[16];
            int gb = (b * LTOK + lane * 1024 + (w_o * 4) * 32 + s_o * 4) * DIMC
                   + head * 16 + c;
#pragma unroll
            for (int j = 0; j < 16; ++j) {
                vr[j] = __ldg(qkv + 2 * MOFF + gb + ((j >> 2) * 32 + (j & 3)) * DIMC);
                co[c2][j] = 0.f;
            }
#pragma unroll
            for (int dh = 0; dh < 5; ++dh) {
                int hs = lane + dh - 2;
                bool ok = (unsigned)hs < 32u;
                int src = hs < 0 ? 0 : (hs > 31 ? 31 : hs);
                float tmp[16];
#pragma unroll
                for (int j = 0; j < 16; ++j)
                    tmp[j] = __shfl_sync(0xFFFFFFFFu, vr[j], src);
                if (ok) {
                    const float* wc = wsm + c * 125 + dh * 25;
#pragma unroll
                    for (int dw = 0; dw < 5; ++dw)
#pragma unroll
                        for (int ds = 0; ds < 5; ++ds) {
                            float wt = wc[dw * 5 + ds];
#pragma unroll
                            for (int w = 0; w < 4; ++w)
#pragma unroll
                                for (int s = 0; s < 4; ++s) {
                                    int ww = w + dw - 2, ss = s + ds - 2;
                                    if (ww >= 0 && ww < 4 && ss >= 0 && ss < 4)
                                        co[c2][w * 4 + s] += wt * tmp[ww * 4 + ss];
                                }
                        }
                }
            }
        }
        // packed fp16x2 store: cbuf[pair=warpid][token]
#pragma unroll
        for (int j = 0; j < 16; ++j) {
            uint32_t pk = pkf16(co[0][j] + bv[0], co[1][j] + bv[1]);
            *(uint32_t*)(sm + SM_CBUF + warpid * 2048 + (lane * 16 + j) * 4) = pk;
        }
    }
    __syncthreads();

    // ================= attention: per-warp 64 q-rows, pipelined flash loop ====
    float o[4][2][4];
    float dn[4][4];     // ones-MMA denominator accumulators (col pairs identical)
#pragma unroll
    for (int mt = 0; mt < 4; ++mt) {
#pragma unroll
        for (int j = 0; j < 4; ++j) dn[mt][j] = 0.f;
#pragma unroll
        for (int nt = 0; nt < 2; ++nt)
#pragma unroll
            for (int j = 0; j < 4; ++j) o[mt][nt][j] = 0.f;
    }

    const int fc = lane & 3;

    // s(0): scores for chunk 0
    float s[2][4][4];
#pragma unroll
    for (int nt = 0; nt < 2; ++nt) {
        int krow = nt * 8 + (lane >> 2);
        uint32_t kh0 = *(const uint32_t*)(sm + SM_KH + qk_off(krow, fc));
        uint32_t kh1 = *(const uint32_t*)(sm + SM_KH + qk_off(krow, 4 + fc));
#pragma unroll
        for (int mt = 0; mt < 4; ++mt) {
#pragma unroll
            for (int j = 0; j < 4; ++j) s[nt][mt][j] = 0.f;
            mma16816(s[nt][mt], qh[mt], kh0, kh1);
        }
    }

#pragma unroll 1
    for (int ch = 0; ch < 32; ++ch) {
        // ---- finalize P(ch) from s(ch) ----
        uint32_t pah[4][4];
#pragma unroll
        for (int nt = 0; nt < 2; ++nt)
#pragma unroll
            for (int mt = 0; mt < 4; ++mt) {
                pah[mt][nt * 2 + 0] = ex2h2(pkf16(s[nt][mt][0], s[nt][mt][1]));
                pah[mt][nt * 2 + 1] = ex2h2(pkf16(s[nt][mt][2], s[nt][mt][3]));
            }

        // ---- S(ch+1): independent MMA stream, overlaps PV(ch) below ----
        if (ch < 31) {
#pragma unroll
            for (int nt = 0; nt < 2; ++nt) {
                int krow = (ch + 1) * 16 + nt * 8 + (lane >> 2);
                uint32_t kh0 = *(const uint32_t*)(sm + SM_KH + qk_off(krow, fc));
                uint32_t kh1 = *(const uint32_t*)(sm + SM_KH + qk_off(krow, 4 + fc));
#pragma unroll
                for (int mt = 0; mt < 4; ++mt) {
#pragma unroll
                    for (int j = 0; j < 4; ++j) s[nt][mt][j] = 0.f;
                    mma16816(s[nt][mt], qh[mt], kh0, kh1);
                }
            }
        }

        // ---- PV(ch): O += Ph*Vh + Ph*Vl ; den += Ph*ones ----
#pragma unroll
        for (int ntd = 0; ntd < 2; ++ntd) {
            int vrow = ntd * 8 + (lane >> 2);
            int kof  = ch * 16 + fc * 2;
            const char* vh = sm + SM_VTH + vrow * 1040 + kof * 2;
            uint32_t vh0 = *(const uint32_t*)vh;
            uint32_t vh1 = *(const uint32_t*)(vh + 16);
            const char* vl = sm + SM_VTL + vrow * 1040 + kof * 2;
            uint32_t vl0 = *(const uint32_t*)vl;
            uint32_t vl1 = *(const uint32_t*)(vl + 16);
#pragma unroll
            for (int mt = 0; mt < 4; ++mt) {
                mma16816(o[mt][ntd], pah[mt], vh0, vh1);
                mma16816(o[mt][ntd], pah[mt], vl0, vl1);
            }
        }
#pragma unroll
        for (int mt = 0; mt < 4; ++mt)
            mma16816(dn[mt], pah[mt], ONESF16X2, ONESF16X2);
    }

    // ================= output: normalize + conv + store =================
#pragma unroll
    for (int mt = 0; mt < 4; ++mt) {
#pragma unroll
        for (int rh = 0; rh < 2; ++rh) {
            int t = warpid * 64 + mt * 16 + (lane >> 2) + rh * 8;
            float inv = 1.0f / dn[mt][rh * 2];   // row-sum; cols identical
            int hi = t >> 4, wi = (t >> 2) & 3, si = t & 3;
            int l  = hi * 1024 + (w_o * 4 + wi) * 32 + s_o * 4 + si;
            float* og = out + (size_t)(b * LTOK + l) * DIMC + head * 16;
#pragma unroll
            for (int ntd = 0; ntd < 2; ++ntd) {
                int dcol = ntd * 8 + fc * 2;
                uint32_t cp = *(const uint32_t*)(sm + SM_CBUF
                                + (ntd * 4 + fc) * 2048 + t * 4);
                float c0 = o[mt][ntd][rh * 2 + 0] * inv + h2f_lo(cp);
                float c1 = o[mt][ntd][rh * 2 + 1] * inv + h2f_hi(cp);
                *(float2*)(og + dcol) = make_float2(c0, c1);
            }
        }
    }
}

extern "C" void kernel_launch(void* const* d_in, const int* in_sizes, int n_in,
                              void* d_out, int out_size)
{
    (void)in_sizes; (void)n_in; (void)out_size;
    const float* qkv  = (const float*)d_in[0];
    const float* w    = (const float*)d_in[1];
    const float* bias = (const float*)d_in[2];
    float* out = (float*)d_out;

    cudaFuncSetAttribute(lepe_attn_hmma,
                         cudaFuncAttributeMaxDynamicSharedMemorySize, SMEM_TOTAL);
    lepe_attn_hmma<<<1024, 256, SMEM_TOTAL>>>(qkv, w, bias, out);
}

// round 17
// speedup vs baseline: 2.3333x; 1.2891x over previous
#include <cuda_runtime.h>
#include <cuda_fp16.h>
#include <cstdint>

#define DIMC   128
#define LTOK   32768
#define QSCALE (0.25f * 1.4426950408889634f)   // HD^-0.5 * log2(e)
#define ONESF16X2 0x3C003C00u                  // (1.0h, 1.0h)

// ---------------- smem byte offsets ----------------
// Qh/Kh: 512 rows x 32B (16 fp16), 16B-chunk XOR swizzle -> conflict-free frags
// VTh/VTl: V^T [16 d][520 keys] fp16 (1040B stride; 512 used)
// wsm: conv weights [16 c][125 taps] fp32
// cbuf (ALIASES Qh after Q-frag load): fp16x2 [8 ch-pairs][512 tokens]
#define SM_QH   0
#define SM_KH   16384
#define SM_VTH  32768
#define SM_VTL  49408
#define SM_WSM  66048
#define SM_CBUF SM_QH
#define SMEM_TOTAL 74048

// ---------------- helpers ----------------
// pack: low 16 bits = fp16(a), high 16 bits = fp16(b)
__device__ __forceinline__ uint32_t pkf16(float a, float b) {
    uint32_t r;
    asm("cvt.rn.f16x2.f32 %0, %1, %2;" : "=r"(r) : "f"(b), "f"(a));
    return r;
}
__device__ __forceinline__ uint32_t ex2h2(uint32_t s) {
    uint32_t r;
    asm("ex2.approx.f16x2 %0, %1;" : "=r"(r) : "r"(s));
    return r;
}
__device__ __forceinline__ float h2f_lo(uint32_t p) {
    return __half2float(__ushort_as_half((unsigned short)(p & 0xFFFFu)));
}
__device__ __forceinline__ float h2f_hi(uint32_t p) {
    return __half2float(__ushort_as_half((unsigned short)(p >> 16)));
}
// swizzled byte offset within a Q/K buffer: row r (0..511), u32 index i (0..7)
__device__ __forceinline__ uint32_t qk_off(int r, int i) {
    return (uint32_t)(r * 32 + ((((i >> 2) ^ (r >> 2)) & 1) << 4) + (i & 3) * 4);
}
// m16n8k16 row.col fp16 MMA, fp32 accumulate in-place
__device__ __forceinline__ void mma16816(float* c, const uint32_t* a,
                                          uint32_t b0, uint32_t b1) {
    asm volatile(
        "mma.sync.aligned.m16n8k16.row.col.f32.f16.f16.f32 "
        "{%0,%1,%2,%3}, {%4,%5,%6,%7}, {%8,%9}, {%0,%1,%2,%3};"
        : "+f"(c[0]), "+f"(c[1]), "+f"(c[2]), "+f"(c[3])
        : "r"(a[0]), "r"(a[1]), "r"(a[2]), "r"(a[3]), "r"(b0), "r"(b1));
}

// =============================== kernel ====================================
__global__ void __launch_bounds__(256, 2)
lepe_attn_hmma(const float* __restrict__ qkv,
               const float* __restrict__ wconv,
               const float* __restrict__ bias,
               float* __restrict__ out)
{
    extern __shared__ char sm[];
    float* wsm = (float*)(sm + SM_WSM);

    const int tid    = threadIdx.x;
    const int warpid = tid >> 5;          // 0..7
    const int lane   = tid & 31;

    const int wh   = blockIdx.x;          // 1024 = 128 windows * 8 heads
    const int head = wh & 7;
    const int win  = wh >> 3;
    const int b    = win >> 6;
    const int w_o  = (win >> 3) & 7;
    const int s_o  = win & 7;
    const int MOFF = 2 * LTOK * DIMC;

    // ======= prologue: coalesced QKV load (4 lanes per token), fp16 convert ===
    // token tt = tk*64 + tid/4, 16B chunk ck = tid%4 -> each warp LDG covers
    // 8 full tokens (16 sectors each touched once).
    {
        const int ck = tid & 3;
#pragma unroll
        for (int tk = 0; tk < 8; ++tk) {
            const int tt = tk * 64 + (tid >> 2);
            const int hi = tt >> 4, wi = (tt >> 2) & 3, si = tt & 3;
            const int l  = hi * 1024 + (w_o * 4 + wi) * 32 + s_o * 4 + si;
            const int gb = (b * LTOK + l) * DIMC + head * 16 + ck * 4;

            float4 q4 = *(const float4*)(qkv + gb);
            float4 k4 = *(const float4*)(qkv + MOFF + gb);
            float4 v4 = *(const float4*)(qkv + 2 * MOFF + gb);

            *(uint32_t*)(sm + SM_QH + qk_off(tt, 2 * ck)) =
                pkf16(q4.x * QSCALE, q4.y * QSCALE);
            *(uint32_t*)(sm + SM_QH + qk_off(tt, 2 * ck + 1)) =
                pkf16(q4.z * QSCALE, q4.w * QSCALE);
            *(uint32_t*)(sm + SM_KH + qk_off(tt, 2 * ck))     = pkf16(k4.x, k4.y);
            *(uint32_t*)(sm + SM_KH + qk_off(tt, 2 * ck + 1)) = pkf16(k4.z, k4.w);

            float vv[4] = {v4.x, v4.y, v4.z, v4.w};
#pragma unroll
            for (int i = 0; i < 4; ++i) {
                const int d = ck * 4 + i;
                uint32_t hp = pkf16(vv[i], 0.f);
                float lo = vv[i] - h2f_lo(hp);
                uint32_t lp = pkf16(lo, 0.f);
                *(unsigned short*)(sm + SM_VTH + d * 1040 + tt * 2) =
                    (unsigned short)(hp & 0xFFFFu);
                *(unsigned short*)(sm + SM_VTL + d * 1040 + tt * 2) =
                    (unsigned short)(lp & 0xFFFFu);
            }
        }
    }
    // conv weights
    for (int i = tid; i < 16 * 125; i += 256) {
        int c = i / 125, tap = i % 125;
        wsm[i] = wconv[(head * 16 + c) * 125 + tap];
    }
    __syncthreads();

    // ================= Q fragments FIRST (Qh smem dies after this) ===========
    uint32_t qh[4][4];
    {
        const int c = lane & 3;
#pragma unroll
        for (int mt = 0; mt < 4; ++mt) {
            int r0 = warpid * 64 + mt * 16 + (lane >> 2);
            qh[mt][0] = *(const uint32_t*)(sm + SM_QH + qk_off(r0,     c));
            qh[mt][1] = *(const uint32_t*)(sm + SM_QH + qk_off(r0 + 8, c));
            qh[mt][2] = *(const uint32_t*)(sm + SM_QH + qk_off(r0,     4 + c));
            qh[mt][3] = *(const uint32_t*)(sm + SM_QH + qk_off(r0 + 8, 4 + c));
        }
    }
    __syncthreads();   // all Q reads done before cbuf overwrites Qh

    // ========= LePE conv: V rows read from VT smem (vh+vl), shuffles =========
    // lane = H row (0..31); warp handles channel pair {2*warpid, 2*warpid+1}
    {
        float co[2][16], bv[2];
        bv[0] = __ldg(bias + head * 16 + warpid * 2);
        bv[1] = __ldg(bias + head * 16 + warpid * 2 + 1);
#pragma unroll
        for (int c2 = 0; c2 < 2; ++c2) {
            const int c = warpid * 2 + c2;
            // 16 consecutive tokens of channel c: 32B from VTh + 32B from VTl
            const uint4* ph = (const uint4*)(sm + SM_VTH + c * 1040 + lane * 32);
            const uint4* pl = (const uint4*)(sm + SM_VTL + c * 1040 + lane * 32);
            uint4 ha = ph[0], hb = ph[1];
            uint4 la = pl[0], lb = pl[1];
            uint32_t hw[8] = {ha.x, ha.y, ha.z, ha.w, hb.x, hb.y, hb.z, hb.w};
            uint32_t lw[8] = {la.x, la.y, la.z, la.w, lb.x, lb.y, lb.z, lb.w};
            float vr[16];
#pragma unroll
            for (int k = 0; k < 8; ++k) {
                vr[2 * k]     = h2f_lo(hw[k]) + h2f_lo(lw[k]);
                vr[2 * k + 1] = h2f_hi(hw[k]) + h2f_hi(lw[k]);
            }
#pragma unroll
            for (int j = 0; j < 16; ++j) co[c2][j] = 0.f;
#pragma unroll
            for (int dh = 0; dh < 5; ++dh) {
                int hs = lane + dh - 2;
                bool ok = (unsigned)hs < 32u;
                int src = hs < 0 ? 0 : (hs > 31 ? 31 : hs);
                float tmp[16];
#pragma unroll
                for (int j = 0; j < 16; ++j)
                    tmp[j] = __shfl_sync(0xFFFFFFFFu, vr[j], src);
                if (ok) {
                    const float* wc = wsm + c * 125 + dh * 25;
#pragma unroll
                    for (int dw = 0; dw < 5; ++dw)
#pragma unroll
                        for (int ds = 0; ds < 5; ++ds) {
                            float wt = wc[dw * 5 + ds];
#pragma unroll
                            for (int w = 0; w < 4; ++w)
#pragma unroll
                                for (int s = 0; s < 4; ++s) {
                                    int ww = w + dw - 2, ss = s + ds - 2;
                                    if (ww >= 0 && ww < 4 && ss >= 0 && ss < 4)
                                        co[c2][w * 4 + s] += wt * tmp[ww * 4 + ss];
                                }
                        }
                }
            }
        }
        // packed fp16x2 store: cbuf[pair=warpid][token]
#pragma unroll
        for (int j = 0; j < 16; ++j) {
            uint32_t pk = pkf16(co[0][j] + bv[0], co[1][j] + bv[1]);
            *(uint32_t*)(sm + SM_CBUF + warpid * 2048 + (lane * 16 + j) * 4) = pk;
        }
    }
    __syncthreads();

    // ================= attention: per-warp 64 q-rows, pipelined flash loop ====
    float o[4][2][4];
    float dn[4][4];     // ones-MMA denominator accumulators (col pairs identical)
#pragma unroll
    for (int mt = 0; mt < 4; ++mt) {
#pragma unroll
        for (int j = 0; j < 4; ++j) dn[mt][j] = 0.f;
#pragma unroll
        for (int nt = 0; nt < 2; ++nt)
#pragma unroll
            for (int j = 0; j < 4; ++j) o[mt][nt][j] = 0.f;
    }

    const int fc = lane & 3;

    // s(0): scores for chunk 0
    float s[2][4][4];
#pragma unroll
    for (int nt = 0; nt < 2; ++nt) {
        int krow = nt * 8 + (lane >> 2);
        uint32_t kh0 = *(const uint32_t*)(sm + SM_KH + qk_off(krow, fc));
        uint32_t kh1 = *(const uint32_t*)(sm + SM_KH + qk_off(krow, 4 + fc));
#pragma unroll
        for (int mt = 0; mt < 4; ++mt) {
#pragma unroll
            for (int j = 0; j < 4; ++j) s[nt][mt][j] = 0.f;
            mma16816(s[nt][mt], qh[mt], kh0, kh1);
        }
    }

#pragma unroll 1
    for (int ch = 0; ch < 32; ++ch) {
        // ---- finalize P(ch) from s(ch) ----
        uint32_t pah[4][4];
#pragma unroll
        for (int nt = 0; nt < 2; ++nt)
#pragma unroll
            for (int mt = 0; mt < 4; ++mt) {
                pah[mt][nt * 2 + 0] = ex2h2(pkf16(s[nt][mt][0], s[nt][mt][1]));
                pah[mt][nt * 2 + 1] = ex2h2(pkf16(s[nt][mt][2], s[nt][mt][3]));
            }

        // ---- S(ch+1): independent MMA stream, overlaps PV(ch) below ----
        if (ch < 31) {
#pragma unroll
            for (int nt = 0; nt < 2; ++nt) {
                int krow = (ch + 1) * 16 + nt * 8 + (lane >> 2);
                uint32_t kh0 = *(const uint32_t*)(sm + SM_KH + qk_off(krow, fc));
                uint32_t kh1 = *(const uint32_t*)(sm + SM_KH + qk_off(krow, 4 + fc));
#pragma unroll
                for (int mt = 0; mt < 4; ++mt) {
#pragma unroll
                    for (int j = 0; j < 4; ++j) s[nt][mt][j] = 0.f;
                    mma16816(s[nt][mt], qh[mt], kh0, kh1);
                }
            }
        }

        // ---- PV(ch): O += Ph*Vh + Ph*Vl ; den += Ph*ones ----
#pragma unroll
        for (int ntd = 0; ntd < 2; ++ntd) {
            int vrow = ntd * 8 + (lane >> 2);
            int kof  = ch * 16 + fc * 2;
            const char* vh = sm + SM_VTH + vrow * 1040 + kof * 2;
            uint32_t vh0 = *(const uint32_t*)vh;
            uint32_t vh1 = *(const uint32_t*)(vh + 16);
            const char* vl = sm + SM_VTL + vrow * 1040 + kof * 2;
            uint32_t vl0 = *(const uint32_t*)vl;
            uint32_t vl1 = *(const uint32_t*)(vl + 16);
#pragma unroll
            for (int mt = 0; mt < 4; ++mt) {
                mma16816(o[mt][ntd], pah[mt], vh0, vh1);
                mma16816(o[mt][ntd], pah[mt], vl0, vl1);
            }
        }
#pragma unroll
        for (int mt = 0; mt < 4; ++mt)
            mma16816(dn[mt], pah[mt], ONESF16X2, ONESF16X2);
    }

    // ================= output: normalize + conv + store =================
#pragma unroll
    for (int mt = 0; mt < 4; ++mt) {
#pragma unroll
        for (int rh = 0; rh < 2; ++rh) {
            int t = warpid * 64 + mt * 16 + (lane >> 2) + rh * 8;
            float inv = 1.0f / dn[mt][rh * 2];   // row-sum; cols identical
            int hi = t >> 4, wi = (t >> 2) & 3, si = t & 3;
            int l  = hi * 1024 + (w_o * 4 + wi) * 32 + s_o * 4 + si;
            float* og = out + (size_t)(b * LTOK + l) * DIMC + head * 16;
#pragma unroll
            for (int ntd = 0; ntd < 2; ++ntd) {
                int dcol = ntd * 8 + fc * 2;
                uint32_t cp = *(const uint32_t*)(sm + SM_CBUF
                                + (ntd * 4 + fc) * 2048 + t * 4);
                float c0 = o[mt][ntd][rh * 2 + 0] * inv + h2f_lo(cp);
                float c1 = o[mt][ntd][rh * 2 + 1] * inv + h2f_hi(cp);
                *(float2*)(og + dcol) = make_float2(c0, c1);
            }
        }
    }
}

extern "C" void kernel_launch(void* const* d_in, const int* in_sizes, int n_in,
                              void* d_out, int out_size)
{
    (void)in_sizes; (void)n_in; (void)out_size;
    const float* qkv  = (const float*)d_in[0];
    const float* w    = (const float*)d_in[1];
    const float* bias = (const float*)d_in[2];
    float* out = (float*)d_out;

    cudaFuncSetAttribute(lepe_attn_hmma,
                         cudaFuncAttributeMaxDynamicSharedMemorySize, SMEM_TOTAL);
    lepe_attn_hmma<<<1024, 256, SMEM_TOTAL>>>(qkv, w, bias, out);
}